// round 15
// baseline (speedup 1.0000x reference)
#include <cuda_runtime.h>

#define N_FRAMES 16384
#define HALF_F   (N_FRAMES / 2)       // 8192
#define NUM_BIN  257
#define NUM_CH   8
#define TOTAL    (N_FRAMES * NUM_BIN)
#define PLANE    (NUM_BIN * NUM_CH)   // 2056 floats per (frame, re/im) plane

// streaming load with 256B L2 fetch-granularity hint (sequential x stream)
__device__ __forceinline__ float4 ldcs4_256(const float* p) {
    float4 v;
    asm volatile("ld.global.cs.L2::256B.v4.f32 {%0,%1,%2,%3}, [%4];"
                 : "=f"(v.x), "=f"(v.y), "=f"(v.z), "=f"(v.w) : "l"(p));
    return v;
}

// 2 frames/thread + 256B hint at high occupancy (6 blocks = 48 warps/SM cap):
// hint-benefit scaled with occupancy in R13->R14; this maximizes the product.
__global__ __launch_bounds__(256, 6) void beamform_kernel(
    const float* __restrict__ x,    // [16384, 2, 257, 8]
    const float* __restrict__ W,    // [24, 2, 257, 8]
    const int* __restrict__ beam,   // [16384] (int32 payload)
    float* __restrict__ out)        // [16384, 2, 257, 1]
{
    // Each thread: half a bin (4 ch) for frame t AND frame t+8192.
    unsigned g    = blockIdx.x * 256u + threadIdx.x;  // < TOTAL exactly
    unsigned e    = g >> 1;                           // (t, bin) with t < 8192
    unsigned half = g & 1u;
    unsigned t    = e / (unsigned)NUM_BIN;
    unsigned bin  = e - t * (unsigned)NUM_BIN;

    // beam gather first: longest dependent chain (beam -> W -> FMA)
    int b0 = __ldg(beam + t);
    int b1 = __ldg(beam + t + HALF_F);

    size_t x0 = ((size_t)t * 2 * PLANE) + (size_t)bin * NUM_CH + half * 4;
    size_t x1 = x0 + (size_t)HALF_F * 2 * PLANE;

    // 4 independent streaming loads, 256B L2 granularity
    float4 xr0 = ldcs4_256(x + x0);
    float4 xi0 = ldcs4_256(x + x0 + PLANE);
    float4 xr1 = ldcs4_256(x + x1);
    float4 xi1 = ldcs4_256(x + x1 + PLANE);

    size_t w0 = ((size_t)b0 * 2 * PLANE) + (size_t)bin * NUM_CH + half * 4;
    size_t w1 = ((size_t)b1 * 2 * PLANE) + (size_t)bin * NUM_CH + half * 4;

    float4 wr0 = __ldg((const float4*)(W + w0));
    float4 wi0 = __ldg((const float4*)(W + w0 + PLANE));
    float4 wr1 = __ldg((const float4*)(W + w1));
    float4 wi1 = __ldg((const float4*)(W + w1 + PLANE));

    float pr0 = xr0.x * wr0.x + xr0.y * wr0.y + xr0.z * wr0.z + xr0.w * wr0.w
              + xi0.x * wi0.x + xi0.y * wi0.y + xi0.z * wi0.z + xi0.w * wi0.w;
    float pi0 = xi0.x * wr0.x + xi0.y * wr0.y + xi0.z * wr0.z + xi0.w * wr0.w
              - (xr0.x * wi0.x + xr0.y * wi0.y + xr0.z * wi0.z + xr0.w * wi0.w);
    float pr1 = xr1.x * wr1.x + xr1.y * wr1.y + xr1.z * wr1.z + xr1.w * wr1.w
              + xi1.x * wi1.x + xi1.y * wi1.y + xi1.z * wi1.z + xi1.w * wi1.w;
    float pi1 = xi1.x * wr1.x + xi1.y * wr1.y + xi1.z * wr1.z + xi1.w * wr1.w
              - (xr1.x * wi1.x + xr1.y * wi1.y + xr1.z * wi1.z + xr1.w * wi1.w);

    // combine with partner lane (other 4 channels)
    pr0 += __shfl_xor_sync(0xffffffffu, pr0, 1);
    pi0 += __shfl_xor_sync(0xffffffffu, pi0, 1);
    pr1 += __shfl_xor_sync(0xffffffffu, pr1, 1);
    pi1 += __shfl_xor_sync(0xffffffffu, pi1, 1);

    // even lane -> out_r, odd lane -> out_i
    size_t o0 = (size_t)t * (2 * NUM_BIN) + bin + half * NUM_BIN;
    size_t o1 = o0 + (size_t)HALF_F * (2 * NUM_BIN);
    __stcs(out + o0, half ? pi0 : pr0);
    __stcs(out + o1, half ? pi1 : pr1);
}

extern "C" void kernel_launch(void* const* d_in, const int* in_sizes, int n_in,
                              void* d_out, int out_size) {
    const float* x    = (const float*)d_in[0];
    const float* W    = (const float*)d_in[1];
    const int*   beam = (const int*)d_in[2];
    float*       out  = (float*)d_out;

    unsigned total_threads = (unsigned)TOTAL;        // 4,210,688 = 16448 * 256
    unsigned threads = 256;
    unsigned blocks = (total_threads + threads - 1) / threads;
    beamform_kernel<<<blocks, threads>>>(x, W, beam, out);
}

// round 16
// speedup vs baseline: 1.0385x; 1.0385x over previous
#include <cuda_runtime.h>

#define N_FRAMES 16384
#define QF       (N_FRAMES / 4)       // 4096
#define NUM_BIN  257
#define NUM_CH   8
#define TOTAL    (N_FRAMES * NUM_BIN)
#define PLANE    (NUM_BIN * NUM_CH)   // 2056 floats per (frame, re/im) plane

// streaming load with 256B L2 fetch-granularity hint (sequential x stream)
__device__ __forceinline__ float4 ldcs4_256(const float* p) {
    float4 v;
    asm volatile("ld.global.cs.L2::256B.v4.f32 {%0,%1,%2,%3}, [%4];"
                 : "=f"(v.x), "=f"(v.y), "=f"(v.z), "=f"(v.w) : "l"(p));
    return v;
}

// All offsets fit in 32 bits (x = 270MB): unsigned index math frees the 64-bit
// address reg pairs, letting the full 16-load batch fit at minBlocks=5 (51 regs,
// 40 warps/SM) — R14's MLP depth at +25% occupancy.
__global__ __launch_bounds__(256, 5) void beamform_kernel(
    const float* __restrict__ x,    // [16384, 2, 257, 8]
    const float* __restrict__ W,    // [24, 2, 257, 8]
    const int* __restrict__ beam,   // [16384] (int32 payload)
    float* __restrict__ out)        // [16384, 2, 257, 1]
{
    // Each thread: half a bin (4 ch) for frames t + k*4096, k = 0..3.
    unsigned g    = blockIdx.x * 256u + threadIdx.x;  // < TOTAL/2 exactly
    unsigned e    = g >> 1;
    unsigned half = g & 1u;
    unsigned t    = e / (unsigned)NUM_BIN;
    unsigned bin  = e - t * (unsigned)NUM_BIN;

    // beam gather first: longest dependent chain (beam -> W -> FMA)
    int b0 = __ldg(beam + t);
    int b1 = __ldg(beam + t + QF);
    int b2 = __ldg(beam + t + 2 * QF);
    int b3 = __ldg(beam + t + 3 * QF);

    const unsigned FSTRIDE = (unsigned)QF * 2u * PLANE;   // floats
    unsigned xb = t * 2u * PLANE + bin * NUM_CH + half * 4u;

    // 16 independent streaming loads — front-batched, 256B L2 granularity
    float4 xr0 = ldcs4_256(x + xb);
    float4 xi0 = ldcs4_256(x + xb + PLANE);
    float4 xr1 = ldcs4_256(x + xb + FSTRIDE);
    float4 xi1 = ldcs4_256(x + xb + FSTRIDE + PLANE);
    float4 xr2 = ldcs4_256(x + xb + 2 * FSTRIDE);
    float4 xi2 = ldcs4_256(x + xb + 2 * FSTRIDE + PLANE);
    float4 xr3 = ldcs4_256(x + xb + 3 * FSTRIDE);
    float4 xi3 = ldcs4_256(x + xb + 3 * FSTRIDE + PLANE);

    unsigned wcol = bin * NUM_CH + half * 4u;
    unsigned w0 = (unsigned)b0 * 2u * PLANE + wcol;
    unsigned w1 = (unsigned)b1 * 2u * PLANE + wcol;
    unsigned w2 = (unsigned)b2 * 2u * PLANE + wcol;
    unsigned w3 = (unsigned)b3 * 2u * PLANE + wcol;

    float4 wr0 = __ldg((const float4*)(W + w0));
    float4 wi0 = __ldg((const float4*)(W + w0 + PLANE));
    float4 wr1 = __ldg((const float4*)(W + w1));
    float4 wi1 = __ldg((const float4*)(W + w1 + PLANE));
    float4 wr2 = __ldg((const float4*)(W + w2));
    float4 wi2 = __ldg((const float4*)(W + w2 + PLANE));
    float4 wr3 = __ldg((const float4*)(W + w3));
    float4 wi3 = __ldg((const float4*)(W + w3 + PLANE));

    float pr0 = xr0.x * wr0.x + xr0.y * wr0.y + xr0.z * wr0.z + xr0.w * wr0.w
              + xi0.x * wi0.x + xi0.y * wi0.y + xi0.z * wi0.z + xi0.w * wi0.w;
    float pi0 = xi0.x * wr0.x + xi0.y * wr0.y + xi0.z * wr0.z + xi0.w * wr0.w
              - (xr0.x * wi0.x + xr0.y * wi0.y + xr0.z * wi0.z + xr0.w * wi0.w);
    float pr1 = xr1.x * wr1.x + xr1.y * wr1.y + xr1.z * wr1.z + xr1.w * wr1.w
              + xi1.x * wi1.x + xi1.y * wi1.y + xi1.z * wi1.z + xi1.w * wi1.w;
    float pi1 = xi1.x * wr1.x + xi1.y * wr1.y + xi1.z * wr1.z + xi1.w * wr1.w
              - (xr1.x * wi1.x + xr1.y * wi1.y + xr1.z * wi1.z + xr1.w * wi1.w);
    float pr2 = xr2.x * wr2.x + xr2.y * wr2.y + xr2.z * wr2.z + xr2.w * wr2.w
              + xi2.x * wi2.x + xi2.y * wi2.y + xi2.z * wi2.z + xi2.w * wi2.w;
    float pi2 = xi2.x * wr2.x + xi2.y * wr2.y + xi2.z * wr2.z + xi2.w * wr2.w
              - (xr2.x * wi2.x + xr2.y * wi2.y + xr2.z * wi2.z + xr2.w * wi2.w);
    float pr3 = xr3.x * wr3.x + xr3.y * wr3.y + xr3.z * wr3.z + xr3.w * wr3.w
              + xi3.x * wi3.x + xi3.y * wi3.y + xi3.z * wi3.z + xi3.w * wi3.w;
    float pi3 = xi3.x * wr3.x + xi3.y * wr3.y + xi3.z * wr3.z + xi3.w * wr3.w
              - (xr3.x * wi3.x + xr3.y * wi3.y + xr3.z * wi3.z + xr3.w * wi3.w);

    // combine with partner lane (other 4 channels)
    pr0 += __shfl_xor_sync(0xffffffffu, pr0, 1);
    pi0 += __shfl_xor_sync(0xffffffffu, pi0, 1);
    pr1 += __shfl_xor_sync(0xffffffffu, pr1, 1);
    pi1 += __shfl_xor_sync(0xffffffffu, pi1, 1);
    pr2 += __shfl_xor_sync(0xffffffffu, pr2, 1);
    pi2 += __shfl_xor_sync(0xffffffffu, pi2, 1);
    pr3 += __shfl_xor_sync(0xffffffffu, pr3, 1);
    pi3 += __shfl_xor_sync(0xffffffffu, pi3, 1);

    // even lane -> out_r, odd lane -> out_i
    const unsigned OSTRIDE = (unsigned)QF * (2u * NUM_BIN);
    unsigned o = t * (2u * NUM_BIN) + bin + half * NUM_BIN;
    __stcs(out + o,               half ? pi0 : pr0);
    __stcs(out + o + OSTRIDE,     half ? pi1 : pr1);
    __stcs(out + o + 2 * OSTRIDE, half ? pi2 : pr2);
    __stcs(out + o + 3 * OSTRIDE, half ? pi3 : pr3);
}

extern "C" void kernel_launch(void* const* d_in, const int* in_sizes, int n_in,
                              void* d_out, int out_size) {
    const float* x    = (const float*)d_in[0];
    const float* W    = (const float*)d_in[1];
    const int*   beam = (const int*)d_in[2];
    float*       out  = (float*)d_out;

    unsigned total_threads = (unsigned)(TOTAL / 2);  // 2,105,344 = 8224 * 256
    unsigned threads = 256;
    unsigned blocks = (total_threads + threads - 1) / threads;
    beamform_kernel<<<blocks, threads>>>(x, W, beam, out);
}